// round 11
// baseline (speedup 1.0000x reference)
#include <cuda_runtime.h>
#include <cuda_bf16.h>
#include <math.h>
#include <stdint.h>

#define T 4096
#define D 2048
#define H 128

// ---------------- scratch (device globals; no allocation allowed) ----------
__device__ __align__(256) __nv_bfloat16 g_xhi[T * D];
__device__ __align__(256) __nv_bfloat16 g_xlo[T * D];
__device__ __align__(256) __nv_bfloat16 g_whi[3 * H * D];
__device__ __align__(256) __nv_bfloat16 g_wlo[3 * H * D];
__device__ __align__(256) __nv_bfloat16 g_qhi[T * H];
__device__ __align__(256) __nv_bfloat16 g_qlo[T * H];
__device__ __align__(256) __nv_bfloat16 g_khi[T * H];
__device__ __align__(256) __nv_bfloat16 g_klo[T * H];
__device__ __align__(256) __nv_bfloat16 g_vhiT[H * T];  // [head][token]
__device__ __align__(256) __nv_bfloat16 g_vloT[H * T];
__device__ __align__(256) float g_s[(size_t)T * T];     // fp32 logits
__device__ __align__(256) __nv_bfloat16 g_phi[(size_t)T * T];
__device__ __align__(256) __nv_bfloat16 g_plo[(size_t)T * T];
__device__ __align__(256) float g_part[9][T * H];       // partials (qkv & pv)

// ---------------------------- PTX helpers ----------------------------------
__device__ __forceinline__ uint32_t smem_u32(const void* p) {
  uint32_t a;
  asm("{ .reg .u64 t; cvta.to.shared.u64 t, %1; cvt.u32.u64 %0, t; }"
      : "=r"(a) : "l"(p));
  return a;
}

__device__ __forceinline__ void cp16(uint32_t dst, const void* src) {
  asm volatile("cp.async.cg.shared.global [%0], [%1], 16;" ::
               "r"(dst), "l"(src) : "memory");
}
#define CP_COMMIT() asm volatile("cp.async.commit_group;" ::: "memory")
#define CP_WAIT(n)  asm volatile("cp.async.wait_group %0;" :: "n"(n) : "memory")

__device__ __forceinline__ void ldsm4(uint32_t* r, uint32_t addr) {
  asm volatile(
      "ldmatrix.sync.aligned.m8n8.x4.shared.b16 {%0,%1,%2,%3}, [%4];"
      : "=r"(r[0]), "=r"(r[1]), "=r"(r[2]), "=r"(r[3]) : "r"(addr));
}

__device__ __forceinline__ void mma_bf16(float* c, const uint32_t* a,
                                         const uint32_t* b) {
  asm volatile(
      "mma.sync.aligned.m16n8k16.row.col.f32.bf16.bf16.f32 "
      "{%0,%1,%2,%3}, {%4,%5,%6,%7}, {%8,%9}, {%0,%1,%2,%3};"
      : "+f"(c[0]), "+f"(c[1]), "+f"(c[2]), "+f"(c[3])
      : "r"(a[0]), "r"(a[1]), "r"(a[2]), "r"(a[3]), "r"(b[0]), "r"(b[1]));
}

struct GemmArgs {
  const __nv_bfloat16 *ahi, *alo, *bhi, *blo;
  int arow0, astride, brow0, bstride, col0, nchunks;
};

// ---------------------------------------------------------------------------
// 256-thread GEMM (R7-proven fragment layout): block tile 128x128, warp grid
// 2(m) x 4(n), warp tile 64x32 (MI=4). K-chunk 64.
// DB=true : intra-CTA double buffer (147456 B SMEM, 1 CTA/SM) — for long-K.
// DB=false: single buffer (73728 B), 2 CTAs/SM cross-overlap — for short-K.
// acc += Ahi*Bhi + Ahi*Blo + Alo*Bhi  (compensated bf16).
// ---------------------------------------------------------------------------
#define SPADC 72                          // 64 + 8 bf16 pad, conflict-free
#define TILE_B (128 * SPADC * 2)          // 18432 B per 128x64 bf16 tile
#define OFF_ALO (TILE_B)
#define OFF_BHI (2 * TILE_B)
#define OFF_BLO (3 * TILE_B)
#define BUF_B (4 * TILE_B)                // 73728 one buffer
#define SMEM_SB (BUF_B)                   // 73728
#define SMEM_DB (2 * BUF_B)               // 147456

__device__ __forceinline__ void load_tile_256(
    uint32_t dst, const __nv_bfloat16* __restrict__ src, int r0, int stride,
    int c0, int tid) {
#pragma unroll
  for (int p = 0; p < 4; p++) {
    int i = tid + (p << 8);        // 0..1023 16B chunks
    int row = i >> 3;              // 0..127
    int col = (i & 7) << 3;        // bf16 col 0..56
    cp16(dst + (uint32_t)(row * SPADC + col) * 2,
         src + (size_t)(r0 + row) * stride + c0 + col);
  }
}

template <bool DB>
__device__ __forceinline__ void gemm_mainloop(float (&acc)[4][4][4],
                                              const GemmArgs& g, uint32_t sb) {
  const int tid = threadIdx.x;
  const int l = tid & 31, w = tid >> 5;
  const int wm = w & 1, wn = w >> 1;

  const uint32_t ra = (uint32_t)(wm * 64 + (l & 15));
  const uint32_t ka = (uint32_t)((l >> 4) << 3);
  const uint32_t rb = (uint32_t)(wn * 32 + (l & 7) + ((l >> 4) << 3));
  const uint32_t kb = (uint32_t)(((l >> 3) & 1) << 3);

  auto load_chunk = [&](int buf, int c0) {
    uint32_t dbase = sb + ((DB && buf) ? BUF_B : 0);
    load_tile_256(dbase, g.ahi, g.arow0, g.astride, c0, tid);
    load_tile_256(dbase + OFF_ALO, g.alo, g.arow0, g.astride, c0, tid);
    load_tile_256(dbase + OFF_BHI, g.bhi, g.brow0, g.bstride, c0, tid);
    load_tile_256(dbase + OFF_BLO, g.blo, g.brow0, g.bstride, c0, tid);
  };

  if (DB) {
    load_chunk(0, g.col0);
    CP_COMMIT();
  }

  int buf = 0;
  for (int kc = 0; kc < g.nchunks; kc++) {
    if (DB) {
      if (kc + 1 < g.nchunks) {
        load_chunk(buf ^ 1, g.col0 + ((kc + 1) << 6));
        CP_COMMIT();
        CP_WAIT(1);
      } else {
        CP_WAIT(0);
      }
    } else {
      load_chunk(0, g.col0 + (kc << 6));
      CP_COMMIT();
      CP_WAIT(0);
    }
    __syncthreads();

    uint32_t base = sb + ((DB && buf) ? BUF_B : 0);
#pragma unroll
    for (int ks = 0; ks < 4; ks++) {
      const uint32_t k0 = ks * 16;
      const uint32_t aHi = base + (ra * SPADC + k0 + ka) * 2;
      const uint32_t aLo = base + OFF_ALO + (ra * SPADC + k0 + ka) * 2;
      const uint32_t bHi = base + OFF_BHI + (rb * SPADC + k0 + kb) * 2;
      const uint32_t bLo = base + OFF_BLO + (rb * SPADC + k0 + kb) * 2;

      uint32_t a[4][4], b[2][4], b2[2][4];
#pragma unroll
      for (int mi = 0; mi < 4; mi++) ldsm4(a[mi], aHi + mi * 16 * SPADC * 2);
#pragma unroll
      for (int j = 0; j < 2; j++) ldsm4(b[j], bHi + j * 16 * SPADC * 2);
      // hi * hi
#pragma unroll
      for (int mi = 0; mi < 4; mi++)
#pragma unroll
        for (int nj = 0; nj < 4; nj++)
          mma_bf16(acc[mi][nj], a[mi], &b[nj >> 1][(nj & 1) << 1]);
      // hi * lo
#pragma unroll
      for (int j = 0; j < 2; j++) ldsm4(b2[j], bLo + j * 16 * SPADC * 2);
#pragma unroll
      for (int mi = 0; mi < 4; mi++)
#pragma unroll
        for (int nj = 0; nj < 4; nj++)
          mma_bf16(acc[mi][nj], a[mi], &b2[nj >> 1][(nj & 1) << 1]);
      // lo * hi
#pragma unroll
      for (int mi = 0; mi < 4; mi++) ldsm4(a[mi], aLo + mi * 16 * SPADC * 2);
#pragma unroll
      for (int mi = 0; mi < 4; mi++)
#pragma unroll
        for (int nj = 0; nj < 4; nj++)
          mma_bf16(acc[mi][nj], a[mi], &b[nj >> 1][(nj & 1) << 1]);
    }
    __syncthreads();
    buf ^= 1;
  }
}

// ---------------------------------------------------------------------------
// Split helpers: fp32 -> bf16 hi + bf16 lo (lo = bf16(x - float(hi)))
// ---------------------------------------------------------------------------
__device__ __forceinline__ void split2(float v, __nv_bfloat16& h,
                                       __nv_bfloat16& l) {
  h = __float2bfloat16(v);
  l = __float2bfloat16(v - __bfloat162float(h));
}
__device__ __forceinline__ uint32_t pack_bf(__nv_bfloat16 a, __nv_bfloat16 b) {
  return (uint32_t)__bfloat16_as_ushort(a) |
         ((uint32_t)__bfloat16_as_ushort(b) << 16);
}

__global__ __launch_bounds__(256) void split_x_kernel(const float* __restrict__ x) {
  int i = (blockIdx.x * 256 + threadIdx.x) << 2;
  float4 v = *(const float4*)(x + i);
  __nv_bfloat16 h0, h1, h2, h3, l0, l1, l2, l3;
  split2(v.x, h0, l0); split2(v.y, h1, l1);
  split2(v.z, h2, l2); split2(v.w, h3, l3);
  *(uint2*)(&g_xhi[i]) = make_uint2(pack_bf(h0, h1), pack_bf(h2, h3));
  *(uint2*)(&g_xlo[i]) = make_uint2(pack_bf(l0, l1), pack_bf(l2, l3));
}

__global__ __launch_bounds__(256) void split_w_kernel(
    const float* __restrict__ wq, const float* __restrict__ wk,
    const float* __restrict__ wv) {
  int wsel = blockIdx.y;
  const float* src = (wsel == 0) ? wq : (wsel == 1) ? wk : wv;
  int i = (blockIdx.x * 256 + threadIdx.x) << 2;
  float4 v = *(const float4*)(src + i);
  __nv_bfloat16 h0, h1, h2, h3, l0, l1, l2, l3;
  split2(v.x, h0, l0); split2(v.y, h1, l1);
  split2(v.z, h2, l2); split2(v.w, h3, l3);
  int o = wsel * (H * D) + i;
  *(uint2*)(&g_whi[o]) = make_uint2(pack_bf(h0, h1), pack_bf(h2, h3));
  *(uint2*)(&g_wlo[o]) = make_uint2(pack_bf(l0, l1), pack_bf(l2, l3));
}

// ---------------------------------------------------------------------------
// QKV: partial C = X[128tile, Kslice] @ W^T, fp32 partials to g_part.
// grid (32 m-tiles, 3 weights, 3 K-splits) = 288 blocks, double-buffered,
// 1 CTA/SM (147 KB SMEM). K slices: 704 / 704 / 640.
// ---------------------------------------------------------------------------
__global__ __launch_bounds__(256) void qkv_mma_kernel() {
  extern __shared__ __align__(16) char sm[];
  uint32_t sb = smem_u32(sm);
  const int mt = blockIdx.x, wsel = blockIdx.y, sk = blockIdx.z;

  GemmArgs g;
  g.ahi = g_xhi; g.alo = g_xlo; g.arow0 = mt * 128; g.astride = D;
  g.bhi = g_whi + wsel * (H * D); g.blo = g_wlo + wsel * (H * D);
  g.brow0 = 0; g.bstride = D;
  g.col0 = sk * 704; g.nchunks = (sk == 2) ? 10 : 11;

  float acc[4][4][4] = {};
  gemm_mainloop<true>(acc, g, sb);

  const int l = threadIdx.x & 31, w = threadIdx.x >> 5;
  const int wm = w & 1, wn = w >> 1;
  float* op = g_part[wsel * 3 + sk];
#pragma unroll
  for (int mi = 0; mi < 4; mi++) {
#pragma unroll
    for (int nj = 0; nj < 4; nj++) {
      int r0 = mt * 128 + wm * 64 + mi * 16 + (l >> 2);
      int c0 = wn * 32 + nj * 8 + ((l & 3) << 1);
      const float* cc = acc[mi][nj];
#pragma unroll
      for (int hh = 0; hh < 2; hh++) {
        int tok = r0 + hh * 8;
        *(float2*)(op + (size_t)tok * H + c0) =
            make_float2(cc[hh * 2 + 0], cc[hh * 2 + 1]);
      }
    }
  }
}

// ---------------------------------------------------------------------------
// Combine Q/K partials (3-way, fixed order), split to bf16 hi/lo. 4 elem/thr.
// ---------------------------------------------------------------------------
__global__ __launch_bounds__(256) void combine_qk_kernel() {
  int idx4 = (blockIdx.x * 256 + threadIdx.x) << 2;  // over 2*T*H
  int wsel = (idx4 >= T * H) ? 1 : 0;
  int rem = idx4 - wsel * (T * H);
  const float* p0 = g_part[wsel * 3 + 0];
  const float* p1 = g_part[wsel * 3 + 1];
  const float* p2 = g_part[wsel * 3 + 2];
  float4 a = *(const float4*)(p0 + rem);
  float4 b = *(const float4*)(p1 + rem);
  float4 c = *(const float4*)(p2 + rem);
  float s0 = a.x + b.x + c.x, s1 = a.y + b.y + c.y;
  float s2 = a.z + b.z + c.z, s3 = a.w + b.w + c.w;
  __nv_bfloat16 h0, l0, h1, l1, h2, l2, h3, l3;
  split2(s0, h0, l0); split2(s1, h1, l1);
  split2(s2, h2, l2); split2(s3, h3, l3);
  uint2 hv = make_uint2(pack_bf(h0, h1), pack_bf(h2, h3));
  uint2 lv = make_uint2(pack_bf(l0, l1), pack_bf(l2, l3));
  if (wsel == 0) {
    *(uint2*)&g_qhi[rem] = hv;
    *(uint2*)&g_qlo[rem] = lv;
  } else {
    *(uint2*)&g_khi[rem] = hv;
    *(uint2*)&g_klo[rem] = lv;
  }
}

// ---------------------------------------------------------------------------
// Combine V partials + transpose to [head][token] via SMEM tile.
// grid (T/64, H/32), 256 threads; tile = 64 tok x 32 heads.
// ---------------------------------------------------------------------------
__global__ __launch_bounds__(256) void combine_v_kernel() {
  __shared__ ushort shi[32][68];
  __shared__ ushort slo[32][68];
  const int t0 = blockIdx.x * 64, c0 = blockIdx.y * 32;
  const int tid = threadIdx.x;
  const float* p0 = g_part[6];
  const float* p1 = g_part[7];
  const float* p2 = g_part[8];

#pragma unroll
  for (int i = 0; i < 2; i++) {
    int idx = tid + (i << 8);       // 0..511
    int r = idx >> 3;               // 0..63 token
    int q4 = (idx & 7) << 2;        // 0..28 head (x4)
    size_t off = (size_t)(t0 + r) * H + c0 + q4;
    float4 a = *(const float4*)(p0 + off);
    float4 b = *(const float4*)(p1 + off);
    float4 c = *(const float4*)(p2 + off);
    float s[4] = {a.x + b.x + c.x, a.y + b.y + c.y, a.z + b.z + c.z,
                  a.w + b.w + c.w};
#pragma unroll
    for (int j = 0; j < 4; j++) {
      __nv_bfloat16 h, l;
      split2(s[j], h, l);
      shi[q4 + j][r] = __bfloat16_as_ushort(h);
      slo[q4 + j][r] = __bfloat16_as_ushort(l);
    }
  }
  __syncthreads();

#pragma unroll
  for (int i = 0; i < 2; i++) {
    int idx = tid + (i << 8);       // 0..511
    int c = idx >> 4;               // 0..31
    int t4 = (idx & 15) << 2;       // 0..60
    uint2 hv = make_uint2(
        (uint32_t)shi[c][t4] | ((uint32_t)shi[c][t4 + 1] << 16),
        (uint32_t)shi[c][t4 + 2] | ((uint32_t)shi[c][t4 + 3] << 16));
    uint2 lv = make_uint2(
        (uint32_t)slo[c][t4] | ((uint32_t)slo[c][t4 + 1] << 16),
        (uint32_t)slo[c][t4 + 2] | ((uint32_t)slo[c][t4 + 3] << 16));
    *(uint2*)&g_vhiT[(size_t)(c0 + c) * T + t0 + t4] = hv;
    *(uint2*)&g_vloT[(size_t)(c0 + c) * T + t0 + t4] = lv;
  }
}

// ---------------------------------------------------------------------------
// Scores: S = Q_it @ K_jt^T * scale, causal mask -> -inf, fp32 out.
// grid (jt=32, it=32), single-buffer, 2 CTAs/SM; jt>it exits.
// ---------------------------------------------------------------------------
__global__ __launch_bounds__(256, 2) void scores_mma_kernel() {
  const int jt = blockIdx.x, it = blockIdx.y;
  if (jt > it) return;
  extern __shared__ __align__(16) char sm[];
  uint32_t sb = smem_u32(sm);

  GemmArgs g;
  g.ahi = g_qhi; g.alo = g_qlo; g.arow0 = it * 128; g.astride = H;
  g.bhi = g_khi; g.blo = g_klo; g.brow0 = jt * 128; g.bstride = H;
  g.col0 = 0; g.nchunks = 2;

  float acc[4][4][4] = {};
  gemm_mainloop<false>(acc, g, sb);

  const int l = threadIdx.x & 31, w = threadIdx.x >> 5;
  const int wm = w & 1, wn = w >> 1;
  const float scale = 0.08838834764831845f;  // 1/sqrt(128)
#pragma unroll
  for (int mi = 0; mi < 4; mi++) {
#pragma unroll
    for (int nj = 0; nj < 4; nj++) {
      int r0 = it * 128 + wm * 64 + mi * 16 + (l >> 2);
      int c0 = jt * 128 + wn * 32 + nj * 8 + ((l & 3) << 1);
      const float* cc = acc[mi][nj];
#pragma unroll
      for (int hh = 0; hh < 2; hh++) {
        int row = r0 + hh * 8;
        float2 v;
        v.x = (c0 + 0 > row) ? -INFINITY : cc[hh * 2 + 0] * scale;
        v.y = (c0 + 1 > row) ? -INFINITY : cc[hh * 2 + 1] * scale;
        *(float2*)(g_s + (size_t)row * T + c0) = v;
      }
    }
  }
}

// ---------------------------------------------------------------------------
// Softmax: fp32 logits -> probabilities re-split to bf16 hi/lo. 1 block/row.
// ---------------------------------------------------------------------------
__global__ __launch_bounds__(256) void softmax_kernel() {
  const int t = blockIdx.x;
  const int ncols = ((t >> 7) + 1) << 7;  // 128-tile-aligned causal end
  const float* row = g_s + (size_t)t * T;
  const int tid = threadIdx.x;

  float vals[16];
  float lmax = -INFINITY;
#pragma unroll
  for (int p = 0; p < 16; p++) {
    int c = tid + (p << 8);
    float v = (c < ncols) ? row[c] : -INFINITY;
    vals[p] = v;
    lmax = fmaxf(lmax, v);
  }

  __shared__ float redm[8];
#pragma unroll
  for (int o = 16; o; o >>= 1) lmax = fmaxf(lmax, __shfl_xor_sync(~0u, lmax, o));
  if ((tid & 31) == 0) redm[tid >> 5] = lmax;
  __syncthreads();
  float m = redm[0];
#pragma unroll
  for (int w = 1; w < 8; w++) m = fmaxf(m, redm[w]);

  float lsum = 0.f;
#pragma unroll
  for (int p = 0; p < 16; p++) {
    float e = __expf(vals[p] - m);
    vals[p] = e;
    lsum += e;
  }

  __shared__ float reds[8];
#pragma unroll
  for (int o = 16; o; o >>= 1) lsum += __shfl_xor_sync(~0u, lsum, o);
  if ((tid & 31) == 0) reds[tid >> 5] = lsum;
  __syncthreads();
  float s = 0.f;
#pragma unroll
  for (int w = 0; w < 8; w++) s += reds[w];

  float inv = 1.0f / s;
  __nv_bfloat16* rh = g_phi + (size_t)t * T;
  __nv_bfloat16* rl = g_plo + (size_t)t * T;
#pragma unroll
  for (int p = 0; p < 16; p++) {
    int c = tid + (p << 8);
    if (c < ncols) {
      __nv_bfloat16 h, l;
      split2(vals[p] * inv, h, l);
      rh[c] = h;
      rl[c] = l;
    }
  }
}

// ---------------------------------------------------------------------------
// PV: partial O = P @ V (split-K chunks of 512 kv positions), CHUNK=64.
// grid (ch=8, it=32), single-buffer, 2 CTAs/SM; empty chunks exit.
// ---------------------------------------------------------------------------
__global__ __launch_bounds__(256, 2) void pv_mma_kernel() {
  const int ch = blockIdx.x, it = blockIdx.y;
  const int kbeg = ch << 9;
  const int klim = (it + 1) << 7;
  if (kbeg >= klim) return;
  const int kend = min(kbeg + 512, klim);
  extern __shared__ __align__(16) char sm[];
  uint32_t sb = smem_u32(sm);

  GemmArgs g;
  g.ahi = g_phi; g.alo = g_plo; g.arow0 = it * 128; g.astride = T;
  g.bhi = g_vhiT; g.blo = g_vloT; g.brow0 = 0; g.bstride = T;
  g.col0 = kbeg; g.nchunks = (kend - kbeg) >> 6;

  float acc[4][4][4] = {};
  gemm_mainloop<false>(acc, g, sb);

  const int l = threadIdx.x & 31, w = threadIdx.x >> 5;
  const int wm = w & 1, wn = w >> 1;
  float* op = g_part[ch];
#pragma unroll
  for (int mi = 0; mi < 4; mi++) {
#pragma unroll
    for (int nj = 0; nj < 4; nj++) {
      int r0 = it * 128 + wm * 64 + mi * 16 + (l >> 2);
      int c0 = wn * 32 + nj * 8 + ((l & 3) << 1);
      const float* cc = acc[mi][nj];
#pragma unroll
      for (int hh = 0; hh < 2; hh++) {
        int row = r0 + hh * 8;
        *(float2*)(op + (size_t)row * H + c0) =
            make_float2(cc[hh * 2 + 0], cc[hh * 2 + 1]);
      }
    }
  }
}

// ---------------------------------------------------------------------------
// Reduce split-K partials (fixed order, only valid chunks per row).
// ---------------------------------------------------------------------------
__global__ __launch_bounds__(256) void reduce_kernel(float* __restrict__ out) {
  int idx = blockIdx.x * 256 + threadIdx.x;  // 0..524287
  int t = idx >> 7;
  int nch = (t >> 9) + 1;
  float s = 0.f;
  for (int c = 0; c < nch; c++) s += g_part[c][idx];
  out[idx] = s;
}

// ---------------------------------------------------------------------------
extern "C" void kernel_launch(void* const* d_in, const int* in_sizes, int n_in,
                              void* d_out, int out_size) {
  (void)in_sizes; (void)n_in; (void)out_size;
  const float* x = (const float*)d_in[0];
  const float* wq = (const float*)d_in[1];
  const float* wk = (const float*)d_in[2];
  const float* wv = (const float*)d_in[3];
  float* out = (float*)d_out;

  cudaFuncSetAttribute(qkv_mma_kernel,
                       cudaFuncAttributeMaxDynamicSharedMemorySize, SMEM_DB);
  cudaFuncSetAttribute(scores_mma_kernel,
                       cudaFuncAttributeMaxDynamicSharedMemorySize, SMEM_SB);
  cudaFuncSetAttribute(pv_mma_kernel,
                       cudaFuncAttributeMaxDynamicSharedMemorySize, SMEM_SB);

  split_x_kernel<<<(T * D / 4) / 256, 256>>>(x);
  split_w_kernel<<<dim3((H * D / 4) / 256, 3), 256>>>(wq, wk, wv);
  qkv_mma_kernel<<<dim3(32, 3, 3), 256, SMEM_DB>>>();
  combine_qk_kernel<<<(2 * T * H / 4) / 256, 256>>>();
  combine_v_kernel<<<dim3(T / 64, H / 32), 256>>>();
  scores_mma_kernel<<<dim3(32, 32), 256, SMEM_SB>>>();
  softmax_kernel<<<T, 256>>>();
  pv_mma_kernel<<<dim3(8, 32), 256, SMEM_SB>>>();
  reduce_kernel<<<(T * H) / 256, 256>>>(out);
}

// round 13
// speedup vs baseline: 1.4666x; 1.4666x over previous
#include <cuda_runtime.h>
#include <cuda_fp16.h>
#include <math.h>
#include <stdint.h>

#define T 4096
#define D 2048
#define H 128

typedef unsigned short u16;

// ---------------- scratch (device globals; no allocation allowed) ----------
__device__ __align__(256) u16 g_xh[T * D];          // X fp16 (single)
__device__ __align__(256) u16 g_whh[3 * H * D];     // W fp16 hi
__device__ __align__(256) u16 g_whl[3 * H * D];     // W fp16 lo
__device__ __align__(256) u16 g_qh[T * H];          // q*scale fp16 (single)
__device__ __align__(256) u16 g_khh[T * H];         // k fp16 hi
__device__ __align__(256) u16 g_khl[T * H];         // k fp16 lo
__device__ __align__(256) u16 g_vhT[H * T];         // V^T fp16 [head][token]
__device__ __align__(256) float g_s[(size_t)T * T]; // fp32 logits
__device__ __align__(256) u16 g_p[(size_t)T * T];   // probs fp16 (single)
__device__ __align__(256) float g_part[9][T * H];   // partials (qkv & pv)

// ---------------------------- PTX helpers ----------------------------------
__device__ __forceinline__ uint32_t smem_u32(const void* p) {
  uint32_t a;
  asm("{ .reg .u64 t; cvta.to.shared.u64 t, %1; cvt.u32.u64 %0, t; }"
      : "=r"(a) : "l"(p));
  return a;
}

__device__ __forceinline__ void cp16(uint32_t dst, const void* src) {
  asm volatile("cp.async.cg.shared.global [%0], [%1], 16;" ::
               "r"(dst), "l"(src) : "memory");
}
#define CP_COMMIT() asm volatile("cp.async.commit_group;" ::: "memory")
#define CP_WAIT(n)  asm volatile("cp.async.wait_group %0;" :: "n"(n) : "memory")

__device__ __forceinline__ void ldsm4(uint32_t* r, uint32_t addr) {
  asm volatile(
      "ldmatrix.sync.aligned.m8n8.x4.shared.b16 {%0,%1,%2,%3}, [%4];"
      : "=r"(r[0]), "=r"(r[1]), "=r"(r[2]), "=r"(r[3]) : "r"(addr));
}

__device__ __forceinline__ void mma_f16(float* c, const uint32_t* a,
                                        const uint32_t* b) {
  asm volatile(
      "mma.sync.aligned.m16n8k16.row.col.f32.f16.f16.f32 "
      "{%0,%1,%2,%3}, {%4,%5,%6,%7}, {%8,%9}, {%0,%1,%2,%3};"
      : "+f"(c[0]), "+f"(c[1]), "+f"(c[2]), "+f"(c[3])
      : "r"(a[0]), "r"(a[1]), "r"(a[2]), "r"(a[3]), "r"(b[0]), "r"(b[1]));
}

// fp16 conversion helpers
__device__ __forceinline__ u16 f2h(float v) {
  return __half_as_ushort(__float2half_rn(v));
}
__device__ __forceinline__ void split2h(float v, u16& h, u16& l) {
  __half hh = __float2half_rn(v);
  h = __half_as_ushort(hh);
  l = f2h(v - __half2float(hh));
}
__device__ __forceinline__ uint32_t pack16(u16 a, u16 b) {
  return (uint32_t)a | ((uint32_t)b << 16);
}

struct GemmArgs {
  const u16 *a, *bh, *bl;
  int arow0, astride, brow0, bstride, col0, nchunks;
};

// ---------------------------------------------------------------------------
// 256-thread GEMM: block tile 128x128, warp grid 2(m) x 4(n), warp tile
// 64x32 (MI=4). K-chunk 64. A = single fp16; B = hi (+ lo if SPLITB).
// acc += A*Bhi (+ A*Blo).  DB: intra-CTA double buffer.
// ---------------------------------------------------------------------------
#define SPADC 72                          // 64 + 8 fp16 pad, conflict-free
#define TILE_B (128 * SPADC * 2)          // 18432 B per 128x64 fp16 tile
#define SMEM_QKV (2 * 3 * TILE_B)         // 110592 (DB, 3 tiles)
#define SMEM_SC  (3 * TILE_B)             // 55296  (SB, 3 tiles)
#define SMEM_PV  (2 * TILE_B)             // 36864  (SB, 2 tiles)

__device__ __forceinline__ void load_tile_256(
    uint32_t dst, const u16* __restrict__ src, int r0, int stride, int c0,
    int tid) {
#pragma unroll
  for (int p = 0; p < 4; p++) {
    int i = tid + (p << 8);        // 0..1023 16B chunks
    int row = i >> 3;              // 0..127
    int col = (i & 7) << 3;        // elem col 0..56
    cp16(dst + (uint32_t)(row * SPADC + col) * 2,
         src + (size_t)(r0 + row) * stride + c0 + col);
  }
}

template <bool DB, bool SPLITB>
__device__ __forceinline__ void gemm_mainloop(float (&acc)[4][4][4],
                                              const GemmArgs& g, uint32_t sb) {
  constexpr int BUF = (SPLITB ? 3 : 2) * TILE_B;
  const int tid = threadIdx.x;
  const int l = tid & 31, w = tid >> 5;
  const int wm = w & 1, wn = w >> 1;

  const uint32_t ra = (uint32_t)(wm * 64 + (l & 15));
  const uint32_t ka = (uint32_t)((l >> 4) << 3);
  const uint32_t rb = (uint32_t)(wn * 32 + (l & 7) + ((l >> 4) << 3));
  const uint32_t kb = (uint32_t)(((l >> 3) & 1) << 3);

  auto load_chunk = [&](int buf, int c0) {
    uint32_t dbase = sb + ((DB && buf) ? BUF : 0);
    load_tile_256(dbase, g.a, g.arow0, g.astride, c0, tid);
    load_tile_256(dbase + TILE_B, g.bh, g.brow0, g.bstride, c0, tid);
    if (SPLITB)
      load_tile_256(dbase + 2 * TILE_B, g.bl, g.brow0, g.bstride, c0, tid);
  };

  if (DB) {
    load_chunk(0, g.col0);
    CP_COMMIT();
  }

  int buf = 0;
  for (int kc = 0; kc < g.nchunks; kc++) {
    if (DB) {
      if (kc + 1 < g.nchunks) {
        load_chunk(buf ^ 1, g.col0 + ((kc + 1) << 6));
        CP_COMMIT();
        CP_WAIT(1);
      } else {
        CP_WAIT(0);
      }
    } else {
      load_chunk(0, g.col0 + (kc << 6));
      CP_COMMIT();
      CP_WAIT(0);
    }
    __syncthreads();

    uint32_t base = sb + ((DB && buf) ? BUF : 0);
#pragma unroll
    for (int ks = 0; ks < 4; ks++) {
      const uint32_t k0 = ks * 16;
      const uint32_t aA = base + (ra * SPADC + k0 + ka) * 2;
      const uint32_t bH = base + TILE_B + (rb * SPADC + k0 + kb) * 2;

      uint32_t a[4][4], b[2][4];
#pragma unroll
      for (int mi = 0; mi < 4; mi++) ldsm4(a[mi], aA + mi * 16 * SPADC * 2);
#pragma unroll
      for (int j = 0; j < 2; j++) ldsm4(b[j], bH + j * 16 * SPADC * 2);
#pragma unroll
      for (int mi = 0; mi < 4; mi++)
#pragma unroll
        for (int nj = 0; nj < 4; nj++)
          mma_f16(acc[mi][nj], a[mi], &b[nj >> 1][(nj & 1) << 1]);
      if (SPLITB) {
        const uint32_t bL = base + 2 * TILE_B + (rb * SPADC + k0 + kb) * 2;
        uint32_t b2[2][4];
#pragma unroll
        for (int j = 0; j < 2; j++) ldsm4(b2[j], bL + j * 16 * SPADC * 2);
#pragma unroll
        for (int mi = 0; mi < 4; mi++)
#pragma unroll
          for (int nj = 0; nj < 4; nj++)
            mma_f16(acc[mi][nj], a[mi], &b2[nj >> 1][(nj & 1) << 1]);
      }
    }
    __syncthreads();
    buf ^= 1;
  }
}

// ---------------------------------------------------------------------------
// Input conversion: X -> fp16 single; W -> fp16 hi + lo.
// ---------------------------------------------------------------------------
__global__ __launch_bounds__(256) void split_x_kernel(const float* __restrict__ x) {
  int i = (blockIdx.x * 256 + threadIdx.x) << 2;
  float4 v = *(const float4*)(x + i);
  *(uint2*)(&g_xh[i]) = make_uint2(pack16(f2h(v.x), f2h(v.y)),
                                   pack16(f2h(v.z), f2h(v.w)));
}

__global__ __launch_bounds__(256) void split_w_kernel(
    const float* __restrict__ wq, const float* __restrict__ wk,
    const float* __restrict__ wv) {
  int wsel = blockIdx.y;
  const float* src = (wsel == 0) ? wq : (wsel == 1) ? wk : wv;
  int i = (blockIdx.x * 256 + threadIdx.x) << 2;
  float4 v = *(const float4*)(src + i);
  u16 h0, h1, h2, h3, l0, l1, l2, l3;
  split2h(v.x, h0, l0); split2h(v.y, h1, l1);
  split2h(v.z, h2, l2); split2h(v.w, h3, l3);
  int o = wsel * (H * D) + i;
  *(uint2*)(&g_whh[o]) = make_uint2(pack16(h0, h1), pack16(h2, h3));
  *(uint2*)(&g_whl[o]) = make_uint2(pack16(l0, l1), pack16(l2, l3));
}

// ---------------------------------------------------------------------------
// QKV: partial C = X[128tile, Kslice] @ (Whi+Wlo)^T, fp32 partials to g_part.
// grid (32 m-tiles, 3 weights, 3 K-splits) = 288 blocks, DB, 2 CTAs/SM.
// K slices: 704 / 704 / 640.
// ---------------------------------------------------------------------------
__global__ __launch_bounds__(256, 2) void qkv_mma_kernel() {
  extern __shared__ __align__(16) char sm[];
  uint32_t sb = smem_u32(sm);
  const int mt = blockIdx.x, wsel = blockIdx.y, sk = blockIdx.z;

  GemmArgs g;
  g.a = g_xh; g.arow0 = mt * 128; g.astride = D;
  g.bh = g_whh + wsel * (H * D); g.bl = g_whl + wsel * (H * D);
  g.brow0 = 0; g.bstride = D;
  g.col0 = sk * 704; g.nchunks = (sk == 2) ? 10 : 11;

  float acc[4][4][4] = {};
  gemm_mainloop<true, true>(acc, g, sb);

  const int l = threadIdx.x & 31, w = threadIdx.x >> 5;
  const int wm = w & 1, wn = w >> 1;
  float* op = g_part[wsel * 3 + sk];
#pragma unroll
  for (int mi = 0; mi < 4; mi++) {
#pragma unroll
    for (int nj = 0; nj < 4; nj++) {
      int r0 = mt * 128 + wm * 64 + mi * 16 + (l >> 2);
      int c0 = wn * 32 + nj * 8 + ((l & 3) << 1);
      const float* cc = acc[mi][nj];
#pragma unroll
      for (int hh = 0; hh < 2; hh++) {
        int tok = r0 + hh * 8;
        *(float2*)(op + (size_t)tok * H + c0) =
            make_float2(cc[hh * 2 + 0], cc[hh * 2 + 1]);
      }
    }
  }
}

// ---------------------------------------------------------------------------
// Combine Q/K partials (3-way, fixed order). Q: *scale -> fp16 single.
// K: -> fp16 hi/lo. 4 elems/thread.
// ---------------------------------------------------------------------------
__global__ __launch_bounds__(256) void combine_qk_kernel() {
  const float SCALE = 0.08838834764831845f;  // 1/sqrt(128)
  int idx4 = (blockIdx.x * 256 + threadIdx.x) << 2;  // over 2*T*H
  int wsel = (idx4 >= T * H) ? 1 : 0;
  int rem = idx4 - wsel * (T * H);
  const float* p0 = g_part[wsel * 3 + 0];
  const float* p1 = g_part[wsel * 3 + 1];
  const float* p2 = g_part[wsel * 3 + 2];
  float4 a = *(const float4*)(p0 + rem);
  float4 b = *(const float4*)(p1 + rem);
  float4 c = *(const float4*)(p2 + rem);
  float s0 = a.x + b.x + c.x, s1 = a.y + b.y + c.y;
  float s2 = a.z + b.z + c.z, s3 = a.w + b.w + c.w;
  if (wsel == 0) {
    *(uint2*)&g_qh[rem] =
        make_uint2(pack16(f2h(s0 * SCALE), f2h(s1 * SCALE)),
                   pack16(f2h(s2 * SCALE), f2h(s3 * SCALE)));
  } else {
    u16 h0, l0, h1, l1, h2, l2, h3, l3;
    split2h(s0, h0, l0); split2h(s1, h1, l1);
    split2h(s2, h2, l2); split2h(s3, h3, l3);
    *(uint2*)&g_khh[rem] = make_uint2(pack16(h0, h1), pack16(h2, h3));
    *(uint2*)&g_khl[rem] = make_uint2(pack16(l0, l1), pack16(l2, l3));
  }
}

// ---------------------------------------------------------------------------
// Combine V partials + transpose to [head][token] fp16 single via SMEM tile.
// grid (T/64, H/32), 256 threads; tile = 64 tok x 32 heads.
// ---------------------------------------------------------------------------
__global__ __launch_bounds__(256) void combine_v_kernel() {
  __shared__ u16 sv[32][68];
  const int t0 = blockIdx.x * 64, c0 = blockIdx.y * 32;
  const int tid = threadIdx.x;
  const float* p0 = g_part[6];
  const float* p1 = g_part[7];
  const float* p2 = g_part[8];

#pragma unroll
  for (int i = 0; i < 2; i++) {
    int idx = tid + (i << 8);       // 0..511
    int r = idx >> 3;               // 0..63 token
    int q4 = (idx & 7) << 2;        // 0..28 head (x4)
    size_t off = (size_t)(t0 + r) * H + c0 + q4;
    float4 a = *(const float4*)(p0 + off);
    float4 b = *(const float4*)(p1 + off);
    float4 c = *(const float4*)(p2 + off);
    sv[q4 + 0][r] = f2h(a.x + b.x + c.x);
    sv[q4 + 1][r] = f2h(a.y + b.y + c.y);
    sv[q4 + 2][r] = f2h(a.z + b.z + c.z);
    sv[q4 + 3][r] = f2h(a.w + b.w + c.w);
  }
  __syncthreads();

#pragma unroll
  for (int i = 0; i < 2; i++) {
    int idx = tid + (i << 8);       // 0..511
    int c = idx >> 4;               // 0..31
    int t4 = (idx & 15) << 2;       // 0..60
    uint2 hv = make_uint2(pack16(sv[c][t4], sv[c][t4 + 1]),
                          pack16(sv[c][t4 + 2], sv[c][t4 + 3]));
    *(uint2*)&g_vhT[(size_t)(c0 + c) * T + t0 + t4] = hv;
  }
}

// ---------------------------------------------------------------------------
// Scores: S = qs_it @ (Khi+Klo)_jt^T (scale pre-folded), mask -> -inf.
// grid (jt=32, it=32), SB, 2 CTAs/SM; jt>it exits.
// ---------------------------------------------------------------------------
__global__ __launch_bounds__(256, 2) void scores_mma_kernel() {
  const int jt = blockIdx.x, it = blockIdx.y;
  if (jt > it) return;
  extern __shared__ __align__(16) char sm[];
  uint32_t sb = smem_u32(sm);

  GemmArgs g;
  g.a = g_qh; g.arow0 = it * 128; g.astride = H;
  g.bh = g_khh; g.bl = g_khl; g.brow0 = jt * 128; g.bstride = H;
  g.col0 = 0; g.nchunks = 2;

  float acc[4][4][4] = {};
  gemm_mainloop<false, true>(acc, g, sb);

  const int l = threadIdx.x & 31, w = threadIdx.x >> 5;
  const int wm = w & 1, wn = w >> 1;
#pragma unroll
  for (int mi = 0; mi < 4; mi++) {
#pragma unroll
    for (int nj = 0; nj < 4; nj++) {
      int r0 = it * 128 + wm * 64 + mi * 16 + (l >> 2);
      int c0 = jt * 128 + wn * 32 + nj * 8 + ((l & 3) << 1);
      const float* cc = acc[mi][nj];
#pragma unroll
      for (int hh = 0; hh < 2; hh++) {
        int row = r0 + hh * 8;
        float2 v;
        v.x = (c0 + 0 > row) ? -INFINITY : cc[hh * 2 + 0];
        v.y = (c0 + 1 > row) ? -INFINITY : cc[hh * 2 + 1];
        *(float2*)(g_s + (size_t)row * T + c0) = v;
      }
    }
  }
}

// ---------------------------------------------------------------------------
// Softmax: fp32 logits -> fp16 probabilities. 1 block/row.
// ---------------------------------------------------------------------------
__global__ __launch_bounds__(256) void softmax_kernel() {
  const int t = blockIdx.x;
  const int ncols = ((t >> 7) + 1) << 7;  // 128-tile-aligned causal end
  const float* row = g_s + (size_t)t * T;
  const int tid = threadIdx.x;

  float vals[16];
  float lmax = -INFINITY;
#pragma unroll
  for (int p = 0; p < 16; p++) {
    int c = tid + (p << 8);
    float v = (c < ncols) ? row[c] : -INFINITY;
    vals[p] = v;
    lmax = fmaxf(lmax, v);
  }

  __shared__ float redm[8];
#pragma unroll
  for (int o = 16; o; o >>= 1) lmax = fmaxf(lmax, __shfl_xor_sync(~0u, lmax, o));
  if ((tid & 31) == 0) redm[tid >> 5] = lmax;
  __syncthreads();
  float m = redm[0];
#pragma unroll
  for (int w = 1; w < 8; w++) m = fmaxf(m, redm[w]);

  float lsum = 0.f;
#pragma unroll
  for (int p = 0; p < 16; p++) {
    float e = __expf(vals[p] - m);
    vals[p] = e;
    lsum += e;
  }

  __shared__ float reds[8];
#pragma unroll
  for (int o = 16; o; o >>= 1) lsum += __shfl_xor_sync(~0u, lsum, o);
  if ((tid & 31) == 0) reds[tid >> 5] = lsum;
  __syncthreads();
  float s = 0.f;
#pragma unroll
  for (int w = 0; w < 8; w++) s += reds[w];

  float inv = 1.0f / s;
  u16* rp = g_p + (size_t)t * T;
#pragma unroll
  for (int p = 0; p < 16; p++) {
    int c = tid + (p << 8);
    if (c < ncols) rp[c] = f2h(vals[p] * inv);
  }
}

// ---------------------------------------------------------------------------
// PV: partial O = P @ V (split-K chunks of 512 kv), single fp16 product.
// grid (ch=8, it=32), SB 2-tile SMEM, 2 CTAs/SM; empty chunks exit.
// ---------------------------------------------------------------------------
__global__ __launch_bounds__(256, 2) void pv_mma_kernel() {
  const int ch = blockIdx.x, it = blockIdx.y;
  const int kbeg = ch << 9;
  const int klim = (it + 1) << 7;
  if (kbeg >= klim) return;
  const int kend = min(kbeg + 512, klim);
  extern __shared__ __align__(16) char sm[];
  uint32_t sb = smem_u32(sm);

  GemmArgs g;
  g.a = g_p; g.arow0 = it * 128; g.astride = T;
  g.bh = g_vhT; g.bl = nullptr; g.brow0 = 0; g.bstride = T;
  g.col0 = kbeg; g.nchunks = (kend - kbeg) >> 6;

  float acc[4][4][4] = {};
  gemm_mainloop<false, false>(acc, g, sb);

  const int l = threadIdx.x & 31, w = threadIdx.x >> 5;
  const int wm = w & 1, wn = w >> 1;
  float* op = g_part[ch];
#pragma unroll
  for (int mi = 0; mi < 4; mi++) {
#pragma unroll
    for (int nj = 0; nj < 4; nj++) {
      int r0 = it * 128 + wm * 64 + mi * 16 + (l >> 2);
      int c0 = wn * 32 + nj * 8 + ((l & 3) << 1);
      const float* cc = acc[mi][nj];
#pragma unroll
      for (int hh = 0; hh < 2; hh++) {
        int row = r0 + hh * 8;
        *(float2*)(op + (size_t)row * H + c0) =
            make_float2(cc[hh * 2 + 0], cc[hh * 2 + 1]);
      }
    }
  }
}

// ---------------------------------------------------------------------------
// Reduce split-K partials (fixed order, only valid chunks per row).
// ---------------------------------------------------------------------------
__global__ __launch_bounds__(256) void reduce_kernel(float* __restrict__ out) {
  int idx = blockIdx.x * 256 + threadIdx.x;  // 0..524287
  int t = idx >> 7;
  int nch = (t >> 9) + 1;
  float s = 0.f;
  for (int c = 0; c < nch; c++) s += g_part[c][idx];
  out[idx] = s;
}

// ---------------------------------------------------------------------------
extern "C" void kernel_launch(void* const* d_in, const int* in_sizes, int n_in,
                              void* d_out, int out_size) {
  (void)in_sizes; (void)n_in; (void)out_size;
  const float* x = (const float*)d_in[0];
  const float* wq = (const float*)d_in[1];
  const float* wk = (const float*)d_in[2];
  const float* wv = (const float*)d_in[3];
  float* out = (float*)d_out;

  cudaFuncSetAttribute(qkv_mma_kernel,
                       cudaFuncAttributeMaxDynamicSharedMemorySize, SMEM_QKV);
  cudaFuncSetAttribute(scores_mma_kernel,
                       cudaFuncAttributeMaxDynamicSharedMemorySize, SMEM_SC);
  cudaFuncSetAttribute(pv_mma_kernel,
                       cudaFuncAttributeMaxDynamicSharedMemorySize, SMEM_PV);

  split_x_kernel<<<(T * D / 4) / 256, 256>>>(x);
  split_w_kernel<<<dim3((H * D / 4) / 256, 3), 256>>>(wq, wk, wv);
  qkv_mma_kernel<<<dim3(32, 3, 3), 256, SMEM_QKV>>>();
  combine_qk_kernel<<<(2 * T * H / 4) / 256, 256>>>();
  combine_v_kernel<<<dim3(T / 64, H / 32), 256>>>();
  scores_mma_kernel<<<dim3(32, 32), 256, SMEM_SC>>>();
  softmax_kernel<<<T, 256>>>();
  pv_mma_kernel<<<dim3(8, 32), 256, SMEM_PV>>>();
  reduce_kernel<<<(T * H) / 256, 256>>>(out);
}

// round 14
// speedup vs baseline: 1.7143x; 1.1689x over previous
#include <cuda_runtime.h>
#include <cuda_fp16.h>
#include <math.h>
#include <stdint.h>

#define T 4096
#define D 2048
#define H 128

typedef unsigned short u16;

// ---------------- scratch (device globals; no allocation allowed) ----------
__device__ __align__(256) u16 g_xh[T * D];          // X fp16 (single)
__device__ __align__(256) u16 g_wh[3 * H * D];      // W fp16 (single)
__device__ __align__(256) u16 g_qh[T * H];          // q*scale fp16 (single)
__device__ __align__(256) u16 g_khh[T * H];         // k fp16 hi
__device__ __align__(256) u16 g_khl[T * H];         // k fp16 lo
__device__ __align__(256) u16 g_vhT[H * T];         // V^T fp16 [head][token]
__device__ __align__(256) float g_s[(size_t)T * T]; // fp32 logits
__device__ __align__(256) u16 g_p[(size_t)T * T];   // probs fp16 (single)
__device__ __align__(256) float g_part[9][T * H];   // partials (qkv & pv)

// ---------------------------- PTX helpers ----------------------------------
__device__ __forceinline__ uint32_t smem_u32(const void* p) {
  uint32_t a;
  asm("{ .reg .u64 t; cvta.to.shared.u64 t, %1; cvt.u32.u64 %0, t; }"
      : "=r"(a) : "l"(p));
  return a;
}

__device__ __forceinline__ void cp16(uint32_t dst, const void* src) {
  asm volatile("cp.async.cg.shared.global [%0], [%1], 16;" ::
               "r"(dst), "l"(src) : "memory");
}
#define CP_COMMIT() asm volatile("cp.async.commit_group;" ::: "memory")
#define CP_WAIT(n)  asm volatile("cp.async.wait_group %0;" :: "n"(n) : "memory")

__device__ __forceinline__ void ldsm4(uint32_t* r, uint32_t addr) {
  asm volatile(
      "ldmatrix.sync.aligned.m8n8.x4.shared.b16 {%0,%1,%2,%3}, [%4];"
      : "=r"(r[0]), "=r"(r[1]), "=r"(r[2]), "=r"(r[3]) : "r"(addr));
}

__device__ __forceinline__ void mma_f16(float* c, const uint32_t* a,
                                        const uint32_t* b) {
  asm volatile(
      "mma.sync.aligned.m16n8k16.row.col.f32.f16.f16.f32 "
      "{%0,%1,%2,%3}, {%4,%5,%6,%7}, {%8,%9}, {%0,%1,%2,%3};"
      : "+f"(c[0]), "+f"(c[1]), "+f"(c[2]), "+f"(c[3])
      : "r"(a[0]), "r"(a[1]), "r"(a[2]), "r"(a[3]), "r"(b[0]), "r"(b[1]));
}

// fp16 conversion helpers
__device__ __forceinline__ u16 f2h(float v) {
  return __half_as_ushort(__float2half_rn(v));
}
__device__ __forceinline__ void split2h(float v, u16& h, u16& l) {
  __half hh = __float2half_rn(v);
  h = __half_as_ushort(hh);
  l = f2h(v - __half2float(hh));
}
__device__ __forceinline__ uint32_t pack16(u16 a, u16 b) {
  return (uint32_t)a | ((uint32_t)b << 16);
}

struct GemmArgs {
  const u16 *a, *bh, *bl;
  int arow0, astride, brow0, bstride, col0, nchunks;
};

// ---------------------------------------------------------------------------
// 256-thread GEMM: block tile 128x128, warp grid 2(m) x 4(n), warp tile
// 64x32 (MI=4). K-chunk 64. A = single fp16; B = hi (+ lo if SPLITB).
// acc += A*Bhi (+ A*Blo).  DB: intra-CTA double buffer.
// ---------------------------------------------------------------------------
#define SPADC 72                          // 64 + 8 fp16 pad, conflict-free
#define TILE_B (128 * SPADC * 2)          // 18432 B per 128x64 fp16 tile
#define SMEM_QKV (2 * 2 * TILE_B)         // 73728 (DB, 2 tiles)
#define SMEM_SC  (3 * TILE_B)             // 55296 (SB, 3 tiles)
#define SMEM_PV  (2 * TILE_B)             // 36864 (SB, 2 tiles)

__device__ __forceinline__ void load_tile_256(
    uint32_t dst, const u16* __restrict__ src, int r0, int stride, int c0,
    int tid) {
#pragma unroll
  for (int p = 0; p < 4; p++) {
    int i = tid + (p << 8);        // 0..1023 16B chunks
    int row = i >> 3;              // 0..127
    int col = (i & 7) << 3;        // elem col 0..56
    cp16(dst + (uint32_t)(row * SPADC + col) * 2,
         src + (size_t)(r0 + row) * stride + c0 + col);
  }
}

template <bool DB, bool SPLITB>
__device__ __forceinline__ void gemm_mainloop(float (&acc)[4][4][4],
                                              const GemmArgs& g, uint32_t sb) {
  constexpr int BUF = (SPLITB ? 3 : 2) * TILE_B;
  const int tid = threadIdx.x;
  const int l = tid & 31, w = tid >> 5;
  const int wm = w & 1, wn = w >> 1;

  const uint32_t ra = (uint32_t)(wm * 64 + (l & 15));
  const uint32_t ka = (uint32_t)((l >> 4) << 3);
  const uint32_t rb = (uint32_t)(wn * 32 + (l & 7) + ((l >> 4) << 3));
  const uint32_t kb = (uint32_t)(((l >> 3) & 1) << 3);

  auto load_chunk = [&](int buf, int c0) {
    uint32_t dbase = sb + ((DB && buf) ? BUF : 0);
    load_tile_256(dbase, g.a, g.arow0, g.astride, c0, tid);
    load_tile_256(dbase + TILE_B, g.bh, g.brow0, g.bstride, c0, tid);
    if (SPLITB)
      load_tile_256(dbase + 2 * TILE_B, g.bl, g.brow0, g.bstride, c0, tid);
  };

  if (DB) {
    load_chunk(0, g.col0);
    CP_COMMIT();
  }

  int buf = 0;
  for (int kc = 0; kc < g.nchunks; kc++) {
    if (DB) {
      if (kc + 1 < g.nchunks) {
        load_chunk(buf ^ 1, g.col0 + ((kc + 1) << 6));
        CP_COMMIT();
        CP_WAIT(1);
      } else {
        CP_WAIT(0);
      }
    } else {
      load_chunk(0, g.col0 + (kc << 6));
      CP_COMMIT();
      CP_WAIT(0);
    }
    __syncthreads();

    uint32_t base = sb + ((DB && buf) ? BUF : 0);
#pragma unroll
    for (int ks = 0; ks < 4; ks++) {
      const uint32_t k0 = ks * 16;
      const uint32_t aA = base + (ra * SPADC + k0 + ka) * 2;
      const uint32_t bH = base + TILE_B + (rb * SPADC + k0 + kb) * 2;

      uint32_t a[4][4], b[2][4];
#pragma unroll
      for (int mi = 0; mi < 4; mi++) ldsm4(a[mi], aA + mi * 16 * SPADC * 2);
#pragma unroll
      for (int j = 0; j < 2; j++) ldsm4(b[j], bH + j * 16 * SPADC * 2);
#pragma unroll
      for (int mi = 0; mi < 4; mi++)
#pragma unroll
        for (int nj = 0; nj < 4; nj++)
          mma_f16(acc[mi][nj], a[mi], &b[nj >> 1][(nj & 1) << 1]);
      if (SPLITB) {
        const uint32_t bL = base + 2 * TILE_B + (rb * SPADC + k0 + kb) * 2;
        uint32_t b2[2][4];
#pragma unroll
        for (int j = 0; j < 2; j++) ldsm4(b2[j], bL + j * 16 * SPADC * 2);
#pragma unroll
        for (int mi = 0; mi < 4; mi++)
#pragma unroll
          for (int nj = 0; nj < 4; nj++)
            mma_f16(acc[mi][nj], a[mi], &b2[nj >> 1][(nj & 1) << 1]);
      }
    }
    __syncthreads();
    buf ^= 1;
  }
}

// ---------------------------------------------------------------------------
// Input conversion: X -> fp16 single; W -> fp16 single.
// ---------------------------------------------------------------------------
__global__ __launch_bounds__(256) void split_x_kernel(const float* __restrict__ x) {
  int i = (blockIdx.x * 256 + threadIdx.x) << 2;
  float4 v = *(const float4*)(x + i);
  *(uint2*)(&g_xh[i]) = make_uint2(pack16(f2h(v.x), f2h(v.y)),
                                   pack16(f2h(v.z), f2h(v.w)));
}

__global__ __launch_bounds__(256) void split_w_kernel(
    const float* __restrict__ wq, const float* __restrict__ wk,
    const float* __restrict__ wv) {
  int wsel = blockIdx.y;
  const float* src = (wsel == 0) ? wq : (wsel == 1) ? wk : wv;
  int i = (blockIdx.x * 256 + threadIdx.x) << 2;
  float4 v = *(const float4*)(src + i);
  int o = wsel * (H * D) + i;
  *(uint2*)(&g_wh[o]) = make_uint2(pack16(f2h(v.x), f2h(v.y)),
                                   pack16(f2h(v.z), f2h(v.w)));
}

// ---------------------------------------------------------------------------
// QKV: partial C = X[128tile, Kslice] @ W^T (single fp16 product),
// fp32 partials to g_part. grid (32, 3, 3) = 288 blocks, DB, 2 CTAs/SM.
// K slices: 704 / 704 / 640.
// ---------------------------------------------------------------------------
__global__ __launch_bounds__(256, 2) void qkv_mma_kernel() {
  extern __shared__ __align__(16) char sm[];
  uint32_t sb = smem_u32(sm);
  const int mt = blockIdx.x, wsel = blockIdx.y, sk = blockIdx.z;

  GemmArgs g;
  g.a = g_xh; g.arow0 = mt * 128; g.astride = D;
  g.bh = g_wh + wsel * (H * D); g.bl = nullptr;
  g.brow0 = 0; g.bstride = D;
  g.col0 = sk * 704; g.nchunks = (sk == 2) ? 10 : 11;

  float acc[4][4][4] = {};
  gemm_mainloop<true, false>(acc, g, sb);

  const int l = threadIdx.x & 31, w = threadIdx.x >> 5;
  const int wm = w & 1, wn = w >> 1;
  float* op = g_part[wsel * 3 + sk];
#pragma unroll
  for (int mi = 0; mi < 4; mi++) {
#pragma unroll
    for (int nj = 0; nj < 4; nj++) {
      int r0 = mt * 128 + wm * 64 + mi * 16 + (l >> 2);
      int c0 = wn * 32 + nj * 8 + ((l & 3) << 1);
      const float* cc = acc[mi][nj];
#pragma unroll
      for (int hh = 0; hh < 2; hh++) {
        int tok = r0 + hh * 8;
        *(float2*)(op + (size_t)tok * H + c0) =
            make_float2(cc[hh * 2 + 0], cc[hh * 2 + 1]);
      }
    }
  }
}

// ---------------------------------------------------------------------------
// Combine Q/K partials (3-way, fixed order). Q: *scale -> fp16 single.
// K: -> fp16 hi/lo. 4 elems/thread.
// ---------------------------------------------------------------------------
__global__ __launch_bounds__(256) void combine_qk_kernel() {
  const float SCALE = 0.08838834764831845f;  // 1/sqrt(128)
  int idx4 = (blockIdx.x * 256 + threadIdx.x) << 2;  // over 2*T*H
  int wsel = (idx4 >= T * H) ? 1 : 0;
  int rem = idx4 - wsel * (T * H);
  const float* p0 = g_part[wsel * 3 + 0];
  const float* p1 = g_part[wsel * 3 + 1];
  const float* p2 = g_part[wsel * 3 + 2];
  float4 a = *(const float4*)(p0 + rem);
  float4 b = *(const float4*)(p1 + rem);
  float4 c = *(const float4*)(p2 + rem);
  float s0 = a.x + b.x + c.x, s1 = a.y + b.y + c.y;
  float s2 = a.z + b.z + c.z, s3 = a.w + b.w + c.w;
  if (wsel == 0) {
    *(uint2*)&g_qh[rem] =
        make_uint2(pack16(f2h(s0 * SCALE), f2h(s1 * SCALE)),
                   pack16(f2h(s2 * SCALE), f2h(s3 * SCALE)));
  } else {
    u16 h0, l0, h1, l1, h2, l2, h3, l3;
    split2h(s0, h0, l0); split2h(s1, h1, l1);
    split2h(s2, h2, l2); split2h(s3, h3, l3);
    *(uint2*)&g_khh[rem] = make_uint2(pack16(h0, h1), pack16(h2, h3));
    *(uint2*)&g_khl[rem] = make_uint2(pack16(l0, l1), pack16(l2, l3));
  }
}

// ---------------------------------------------------------------------------
// Combine V partials + transpose to [head][token] fp16 single via SMEM tile.
// grid (T/64, H/32), 256 threads; tile = 64 tok x 32 heads.
// ---------------------------------------------------------------------------
__global__ __launch_bounds__(256) void combine_v_kernel() {
  __shared__ u16 sv[32][68];
  const int t0 = blockIdx.x * 64, c0 = blockIdx.y * 32;
  const int tid = threadIdx.x;
  const float* p0 = g_part[6];
  const float* p1 = g_part[7];
  const float* p2 = g_part[8];

#pragma unroll
  for (int i = 0; i < 2; i++) {
    int idx = tid + (i << 8);       // 0..511
    int r = idx >> 3;               // 0..63 token
    int q4 = (idx & 7) << 2;        // 0..28 head (x4)
    size_t off = (size_t)(t0 + r) * H + c0 + q4;
    float4 a = *(const float4*)(p0 + off);
    float4 b = *(const float4*)(p1 + off);
    float4 c = *(const float4*)(p2 + off);
    sv[q4 + 0][r] = f2h(a.x + b.x + c.x);
    sv[q4 + 1][r] = f2h(a.y + b.y + c.y);
    sv[q4 + 2][r] = f2h(a.z + b.z + c.z);
    sv[q4 + 3][r] = f2h(a.w + b.w + c.w);
  }
  __syncthreads();

#pragma unroll
  for (int i = 0; i < 2; i++) {
    int idx = tid + (i << 8);       // 0..511
    int c = idx >> 4;               // 0..31
    int t4 = (idx & 15) << 2;       // 0..60
    uint2 hv = make_uint2(pack16(sv[c][t4], sv[c][t4 + 1]),
                          pack16(sv[c][t4 + 2], sv[c][t4 + 3]));
    *(uint2*)&g_vhT[(size_t)(c0 + c) * T + t0 + t4] = hv;
  }
}

// ---------------------------------------------------------------------------
// Scores: S = qs_it @ (Khi+Klo)_jt^T (scale pre-folded), mask -> -inf.
// grid (jt=32, it=32), SB, 2 CTAs/SM; jt>it exits.
// ---------------------------------------------------------------------------
__global__ __launch_bounds__(256, 2) void scores_mma_kernel() {
  const int jt = blockIdx.x, it = blockIdx.y;
  if (jt > it) return;
  extern __shared__ __align__(16) char sm[];
  uint32_t sb = smem_u32(sm);

  GemmArgs g;
  g.a = g_qh; g.arow0 = it * 128; g.astride = H;
  g.bh = g_khh; g.bl = g_khl; g.brow0 = jt * 128; g.bstride = H;
  g.col0 = 0; g.nchunks = 2;

  float acc[4][4][4] = {};
  gemm_mainloop<false, true>(acc, g, sb);

  const int l = threadIdx.x & 31, w = threadIdx.x >> 5;
  const int wm = w & 1, wn = w >> 1;
#pragma unroll
  for (int mi = 0; mi < 4; mi++) {
#pragma unroll
    for (int nj = 0; nj < 4; nj++) {
      int r0 = it * 128 + wm * 64 + mi * 16 + (l >> 2);
      int c0 = jt * 128 + wn * 32 + nj * 8 + ((l & 3) << 1);
      const float* cc = acc[mi][nj];
#pragma unroll
      for (int hh = 0; hh < 2; hh++) {
        int row = r0 + hh * 8;
        float2 v;
        v.x = (c0 + 0 > row) ? -INFINITY : cc[hh * 2 + 0];
        v.y = (c0 + 1 > row) ? -INFINITY : cc[hh * 2 + 1];
        *(float2*)(g_s + (size_t)row * T + c0) = v;
      }
    }
  }
}

// ---------------------------------------------------------------------------
// Softmax: fp32 logits -> fp16 probabilities. 1 block/row.
// ---------------------------------------------------------------------------
__global__ __launch_bounds__(256) void softmax_kernel() {
  const int t = blockIdx.x;
  const int ncols = ((t >> 7) + 1) << 7;  // 128-tile-aligned causal end
  const float* row = g_s + (size_t)t * T;
  const int tid = threadIdx.x;

  float vals[16];
  float lmax = -INFINITY;
#pragma unroll
  for (int p = 0; p < 16; p++) {
    int c = tid + (p << 8);
    float v = (c < ncols) ? row[c] : -INFINITY;
    vals[p] = v;
    lmax = fmaxf(lmax, v);
  }

  __shared__ float redm[8];
#pragma unroll
  for (int o = 16; o; o >>= 1) lmax = fmaxf(lmax, __shfl_xor_sync(~0u, lmax, o));
  if ((tid & 31) == 0) redm[tid >> 5] = lmax;
  __syncthreads();
  float m = redm[0];
#pragma unroll
  for (int w = 1; w < 8; w++) m = fmaxf(m, redm[w]);

  float lsum = 0.f;
#pragma unroll
  for (int p = 0; p < 16; p++) {
    float e = __expf(vals[p] - m);
    vals[p] = e;
    lsum += e;
  }

  __shared__ float reds[8];
#pragma unroll
  for (int o = 16; o; o >>= 1) lsum += __shfl_xor_sync(~0u, lsum, o);
  if ((tid & 31) == 0) reds[tid >> 5] = lsum;
  __syncthreads();
  float s = 0.f;
#pragma unroll
  for (int w = 0; w < 8; w++) s += reds[w];

  float inv = 1.0f / s;
  u16* rp = g_p + (size_t)t * T;
#pragma unroll
  for (int p = 0; p < 16; p++) {
    int c = tid + (p << 8);
    if (c < ncols) rp[c] = f2h(vals[p] * inv);
  }
}

// ---------------------------------------------------------------------------
// PV: partial O = P @ V (split-K chunks of 512 kv), single fp16 product.
// grid (ch=8, it=32), SB 2-tile SMEM, 2 CTAs/SM; empty chunks exit.
// ---------------------------------------------------------------------------
__global__ __launch_bounds__(256, 2) void pv_mma_kernel() {
  const int ch = blockIdx.x, it = blockIdx.y;
  const int kbeg = ch << 9;
  const int klim = (it + 1) << 7;
  if (kbeg >= klim) return;
  const int kend = min(kbeg + 512, klim);
  extern __shared__ __align__(16) char sm[];
  uint32_t sb = smem_u32(sm);

  GemmArgs g;
  g.a = g_p; g.arow0 = it * 128; g.astride = T;
  g.bh = g_vhT; g.bl = nullptr; g.brow0 = 0; g.bstride = T;
  g.col0 = kbeg; g.nchunks = (kend - kbeg) >> 6;

  float acc[4][4][4] = {};
  gemm_mainloop<false, false>(acc, g, sb);

  const int l = threadIdx.x & 31, w = threadIdx.x >> 5;
  const int wm = w & 1, wn = w >> 1;
  float* op = g_part[ch];
#pragma unroll
  for (int mi = 0; mi < 4; mi++) {
#pragma unroll
    for (int nj = 0; nj < 4; nj++) {
      int r0 = it * 128 + wm * 64 + mi * 16 + (l >> 2);
      int c0 = wn * 32 + nj * 8 + ((l & 3) << 1);
      const float* cc = acc[mi][nj];
#pragma unroll
      for (int hh = 0; hh < 2; hh++) {
        int row = r0 + hh * 8;
        *(float2*)(op + (size_t)row * H + c0) =
            make_float2(cc[hh * 2 + 0], cc[hh * 2 + 1]);
      }
    }
  }
}

// ---------------------------------------------------------------------------
// Reduce split-K partials (fixed order, only valid chunks per row).
// ---------------------------------------------------------------------------
__global__ __launch_bounds__(256) void reduce_kernel(float* __restrict__ out) {
  int idx = blockIdx.x * 256 + threadIdx.x;  // 0..524287
  int t = idx >> 7;
  int nch = (t >> 9) + 1;
  float s = 0.f;
  for (int c = 0; c < nch; c++) s += g_part[c][idx];
  out[idx] = s;
}

// ---------------------------------------------------------------------------
extern "C" void kernel_launch(void* const* d_in, const int* in_sizes, int n_in,
                              void* d_out, int out_size) {
  (void)in_sizes; (void)n_in; (void)out_size;
  const float* x = (const float*)d_in[0];
  const float* wq = (const float*)d_in[1];
  const float* wk = (const float*)d_in[2];
  const float* wv = (const float*)d_in[3];
  float* out = (float*)d_out;

  cudaFuncSetAttribute(qkv_mma_kernel,
                       cudaFuncAttributeMaxDynamicSharedMemorySize, SMEM_QKV);
  cudaFuncSetAttribute(scores_mma_kernel,
                       cudaFuncAttributeMaxDynamicSharedMemorySize, SMEM_SC);
  cudaFuncSetAttribute(pv_mma_kernel,
                       cudaFuncAttributeMaxDynamicSharedMemorySize, SMEM_PV);

  split_x_kernel<<<(T * D / 4) / 256, 256>>>(x);
  split_w_kernel<<<dim3((H * D / 4) / 256, 3), 256>>>(wq, wk, wv);
  qkv_mma_kernel<<<dim3(32, 3, 3), 256, SMEM_QKV>>>();
  combine_qk_kernel<<<(2 * T * H / 4) / 256, 256>>>();
  combine_v_kernel<<<dim3(T / 64, H / 32), 256>>>();
  scores_mma_kernel<<<dim3(32, 32), 256, SMEM_SC>>>();
  softmax_kernel<<<T, 256>>>();
  pv_mma_kernel<<<dim3(8, 32), 256, SMEM_PV>>>();
  reduce_kernel<<<(T * H) / 256, 256>>>(out);
}